// round 10
// baseline (speedup 1.0000x reference)
#include <cuda_runtime.h>
#include <cuda_bf16.h>
#include <mma.h>

#define NWIN  64
#define NHEAD 12
#define LWIN  343
#define DIMM  384
#define HEADD 32
#define TBL   2197
#define MROWS (NWIN * LWIN)            // 21952
#define QK_SCALE 0.1767766952966369f   // 32^-0.5
#define MWPR  12
#define BJ    352
#define BI    344
#define SPAD  24                       // smem row stride (bf16): 48B (mult of 16B)
#define CPAD  36                       // epilogue f32 stride: 144B (mult of 16B)

typedef unsigned long long u64;
typedef __nv_bfloat16 bf16;
using namespace nvcuda;

// --- device globals: ONLY referenced inside device code, never passed from host ---
__device__ __align__(16) float g_q [NWIN * NHEAD * LWIN * HEADD];
__device__ __align__(16) float g_k [NWIN * NHEAD * LWIN * HEADD];
__device__ __align__(16) float g_v [NWIN * NHEAD * LWIN * HEADD];
__device__ __align__(16) float g_ao[MROWS * DIMM];
__device__ __align__(16) float g_bias[NHEAD * BJ * BI];
__device__ int g_mask_mode;
__device__ unsigned g_maskbits[NWIN * LWIN * MWPR];

__device__ __align__(16) bf16 g_x_hi [MROWS * DIMM];
__device__ __align__(16) bf16 g_x_lo [MROWS * DIMM];
__device__ __align__(16) bf16 g_ao_hi[MROWS * DIMM];
__device__ __align__(16) bf16 g_ao_lo[MROWS * DIMM];
__device__ __align__(16) bf16 g_wq_hi[3 * DIMM * DIMM];   // qkv_w^T  [1152][384]
__device__ __align__(16) bf16 g_wq_lo[3 * DIMM * DIMM];
__device__ __align__(16) bf16 g_wp_hi[DIMM * DIMM];       // proj_w^T [384][384]
__device__ __align__(16) bf16 g_wp_lo[DIMM * DIMM];

union F4U { float4 f; u64 u[2]; };

__device__ __forceinline__ u64 pack2(float a, float b) {
    u64 r; asm("mov.b64 %0,{%1,%2};" : "=l"(r) : "f"(a), "f"(b)); return r;
}
__device__ __forceinline__ float2 unpk2(u64 v) {
    float2 r; asm("mov.b64 {%0,%1},%2;" : "=f"(r.x), "=f"(r.y) : "l"(v)); return r;
}
__device__ __forceinline__ void fma2(u64& d, u64 a, u64 b) {
    asm("fma.rn.f32x2 %0,%1,%2,%0;" : "+l"(d) : "l"(a), "l"(b));
}
__device__ __forceinline__ void mul2(u64& d, u64 s) {
    asm("mul.rn.f32x2 %0,%0,%1;" : "+l"(d) : "l"(s));
}

// ---------------------------------------------------------------------------
// mask detect / bit-pack / bias precompute (proven)
// ---------------------------------------------------------------------------
__global__ void detect_mask_kernel(const unsigned int* __restrict__ m)
{
    if (threadIdx.x == 0) {
        bool sawF32 = false, sawHigh = false;
        for (int i = 0; i < 256; i++) {
            unsigned w = m[i];
            if (w == 0x3F800000u) sawF32 = true;
            else if (w != 0u && w != 1u) sawHigh = true;
        }
        int mode = 1;
        if (sawHigh) mode = 0;
        else if (sawF32) mode = 2;
        g_mask_mode = mode;
    }
}

__global__ __launch_bounds__(256)
void convert_mask_kernel(const void* __restrict__ mraw)
{
    int idx = blockIdx.x * blockDim.x + threadIdx.x;
    if (idx >= NWIN * LWIN * MWPR) return;
    int wi  = idx % MWPR;
    int row = idx / MWPR;
    size_t base = (size_t)(row / LWIN) * LWIN * LWIN + (size_t)(row % LWIN) * LWIN;
    const int mode = g_mask_mode;
    unsigned bits = 0;
    for (int b = 0; b < 32; b++) {
        int j = wi * 32 + b;
        bool mb;
        if (j >= LWIN)          mb = true;
        else if (mode == 0)     mb = ((const unsigned char*)mraw)[base + j] != 0;
        else if (mode == 1)     mb = ((const int*)mraw)[base + j] != 0;
        else                    mb = ((const float*)mraw)[base + j] != 0.0f;
        bits |= (mb ? 1u : 0u) << b;
    }
    g_maskbits[idx] = bits;
}

__global__ __launch_bounds__(BI)
void bias_kernel(const int* __restrict__ rel_idx, const float* __restrict__ table)
{
    int h = blockIdx.x / BJ, j = blockIdx.x % BJ;
    int i = threadIdx.x;
    float v = 0.0f;
    if (j < LWIN && i < LWIN)
        v = __ldg(table + (size_t)__ldg(rel_idx + (size_t)i * LWIN + j) * NHEAD + h);
    g_bias[((size_t)h * BJ + j) * BI + i] = v;
}

// ---------------------------------------------------------------------------
// hi/lo splits. mode 0: in = x (arg) -> g_x_*;  mode 1: in = g_ao -> g_ao_*.
// ---------------------------------------------------------------------------
__global__ __launch_bounds__(256)
void split_kernel(const float* __restrict__ xin, int mode)
{
    const int n4 = MROWS * DIMM / 4;
    int i = blockIdx.x * 256 + threadIdx.x;
    if (i >= n4) return;
    const float* in = mode ? g_ao : xin;
    bf16* hi = mode ? g_ao_hi : g_x_hi;
    bf16* lo = mode ? g_ao_lo : g_x_lo;
    float4 v = ((const float4*)in)[i];
    bf16 h0 = __float2bfloat16(v.x), h1 = __float2bfloat16(v.y);
    bf16 h2 = __float2bfloat16(v.z), h3 = __float2bfloat16(v.w);
    bf16 l0 = __float2bfloat16(v.x - __bfloat162float(h0));
    bf16 l1 = __float2bfloat16(v.y - __bfloat162float(h1));
    bf16 l2 = __float2bfloat16(v.z - __bfloat162float(h2));
    bf16 l3 = __float2bfloat16(v.w - __bfloat162float(h3));
    ((__nv_bfloat162*)hi)[i * 2]     = __nv_bfloat162(h0, h1);
    ((__nv_bfloat162*)hi)[i * 2 + 1] = __nv_bfloat162(h2, h3);
    ((__nv_bfloat162*)lo)[i * 2]     = __nv_bfloat162(l0, l1);
    ((__nv_bfloat162*)lo)[i * 2 + 1] = __nv_bfloat162(l2, l3);
}

// transpose+split weights: in[K=384][N] -> (g_wq_*|g_wp_*)[N][384]. mode 0: qkv, 1: proj.
__global__ __launch_bounds__(256)
void tsplit_kernel(const float* __restrict__ in, int mode)
{
    __shared__ float tile[32][33];
    const int N = mode ? DIMM : 3 * DIMM;
    bf16* hi = mode ? g_wp_hi : g_wq_hi;
    bf16* lo = mode ? g_wp_lo : g_wq_lo;
    int n0 = blockIdx.x * 32, k0 = blockIdx.y * 32;
    int tx = threadIdx.x, ty = threadIdx.y;
#pragma unroll
    for (int i = 0; i < 32; i += 8)
        tile[ty + i][tx] = in[(size_t)(k0 + ty + i) * N + n0 + tx];
    __syncthreads();
#pragma unroll
    for (int i = 0; i < 32; i += 8) {
        float v = tile[tx][ty + i];
        bf16 h = __float2bfloat16(v);
        bf16 l = __float2bfloat16(v - __bfloat162float(h));
        size_t o = (size_t)(n0 + ty + i) * DIMM + k0 + tx;
        hi[o] = h; lo[o] = l;
    }
}

// ---------------------------------------------------------------------------
// bf16x3 WMMA GEMM with fused epilogue.
// mode 0: x @ wq^T (N=1152), scatter into g_q/g_k/g_v (Q pre-scaled)
// mode 1: ao @ wp^T (N=384), + proj_b -> out
// Block 64x128, 256 thr (8 warps, warp tile 32x32).
// dyn smem: mainloop 18432B; epilogue 8 warps * 32*CPAD f32 = 36864B.
// ---------------------------------------------------------------------------
#define WMMA_SMEM_BYTES (8 * 32 * CPAD * 4)   // 36864

__global__ __launch_bounds__(256)
void wmma_gemm_kernel(int mode, const float* __restrict__ pb,
                      float* __restrict__ out)
{
    extern __shared__ __align__(16) char dsm[];
    bf16* AsH = (bf16*)dsm;                  // 64*SPAD
    bf16* AsL = AsH + 64 * SPAD;
    bf16* BsH = AsL + 64 * SPAD;             // 128*SPAD
    bf16* BsL = BsH + 128 * SPAD;
    float* Cs = (float*)dsm;                 // reused after mainloop: 8*32*CPAD

    const bf16* Ahi = mode ? g_ao_hi : g_x_hi;
    const bf16* Alo = mode ? g_ao_lo : g_x_lo;
    const bf16* Bhi = mode ? g_wp_hi : g_wq_hi;
    const bf16* Blo = mode ? g_wp_lo : g_wq_lo;

    const int m0 = blockIdx.y * 64, n0 = blockIdx.x * 128;
    const int tid = threadIdx.x;
    const int lane = tid & 31, w = tid >> 5;
    const int wm = w >> 2, wn = w & 3;
    const int srow = tid >> 1, shalf = tid & 1;

    wmma::fragment<wmma::accumulator, 16, 16, 16, float> c[2][2];
#pragma unroll
    for (int i = 0; i < 2; i++)
#pragma unroll
        for (int j = 0; j < 2; j++) wmma::fill_fragment(c[i][j], 0.0f);

    for (int k0 = 0; k0 < DIMM; k0 += 16) {
        if (tid < 128) {
            size_t go = (size_t)(m0 + srow) * DIMM + k0 + shalf * 8;
            *(uint4*)&AsH[srow * SPAD + shalf * 8] = *(const uint4*)&Ahi[go];
            *(uint4*)&AsL[srow * SPAD + shalf * 8] = *(const uint4*)&Alo[go];
        }
        {
            size_t go = (size_t)(n0 + srow) * DIMM + k0 + shalf * 8;
            *(uint4*)&BsH[srow * SPAD + shalf * 8] = *(const uint4*)&Bhi[go];
            *(uint4*)&BsL[srow * SPAD + shalf * 8] = *(const uint4*)&Blo[go];
        }
        __syncthreads();

        wmma::fragment<wmma::matrix_a, 16, 16, 16, bf16, wmma::row_major> aH[2], aL[2];
        wmma::fragment<wmma::matrix_b, 16, 16, 16, bf16, wmma::col_major> bH[2], bL[2];
#pragma unroll
        for (int i = 0; i < 2; i++) {
            wmma::load_matrix_sync(aH[i], &AsH[(wm * 32 + i * 16) * SPAD], SPAD);
            wmma::load_matrix_sync(aL[i], &AsL[(wm * 32 + i * 16) * SPAD], SPAD);
        }
#pragma unroll
        for (int j = 0; j < 2; j++) {
            wmma::load_matrix_sync(bH[j], &BsH[(wn * 32 + j * 16) * SPAD], SPAD);
            wmma::load_matrix_sync(bL[j], &BsL[(wn * 32 + j * 16) * SPAD], SPAD);
        }
#pragma unroll
        for (int i = 0; i < 2; i++)
#pragma unroll
            for (int j = 0; j < 2; j++) {
                wmma::mma_sync(c[i][j], aH[i], bH[j], c[i][j]);
                wmma::mma_sync(c[i][j], aH[i], bL[j], c[i][j]);
                wmma::mma_sync(c[i][j], aL[i], bH[j], c[i][j]);
            }
        __syncthreads();
    }

    // epilogue: fragments -> Cs (per-warp 32xCPAD tile, ldm mult of 16B) -> writeout
    float* ct = Cs + w * (32 * CPAD);
#pragma unroll
    for (int i = 0; i < 2; i++)
#pragma unroll
        for (int j = 0; j < 2; j++)
            wmma::store_matrix_sync(ct + i * 16 * CPAD + j * 16, c[i][j], CPAD,
                                    wmma::mem_row_major);
    __syncwarp();

    const int colbase = n0 + wn * 32;     // multiple of 32 -> head aligned
    if (mode == 0) {
        const int three = colbase / DIMM;
        const int cm = colbase - three * DIMM;
        const int h = cm >> 5;
        float* dst = (three == 0) ? g_q : (three == 1 ? g_k : g_v);
        const float sc = (three == 0) ? QK_SCALE : 1.0f;
#pragma unroll 4
        for (int r = 0; r < 32; r++) {
            int mg = m0 + wm * 32 + r;
            int n = mg / LWIN, l = mg - n * LWIN;
            dst[(size_t)((n * NHEAD + h) * LWIN + l) * HEADD + lane] =
                ct[r * CPAD + lane] * sc;
        }
    } else {
        const float bv = pb[colbase + lane];
#pragma unroll 4
        for (int r = 0; r < 32; r++) {
            int mg = m0 + wm * 32 + r;
            out[(size_t)mg * DIMM + colbase + lane] = ct[r * CPAD + lane] + bv;
        }
    }
}

// ---------------------------------------------------------------------------
// K2: flash attention, chunk=16, 2 CTAs/SM. grid(12,64), 352 thr.
// ---------------------------------------------------------------------------
#define ATTN_SMEM_BYTES (BJ * HEADD * 2 * 4)   // 90112

__global__ __launch_bounds__(BJ, 2)
void attn_kernel()
{
    extern __shared__ float smem[];
    float* Ks = smem;
    float* Vs = smem + BJ * HEADD;

    const int h   = blockIdx.x;
    const int win = blockIdx.y;
    const int tid = threadIdx.x;
    const int rowc = (tid < LWIN) ? tid : (LWIN - 1);
    const size_t base = (size_t)(win * NHEAD + h) * LWIN * HEADD;

    for (int idx = tid; idx < LWIN * HEADD; idx += BJ) {
        Ks[idx] = g_k[base + idx];
        Vs[idx] = g_v[base + idx];
    }
    for (int idx = LWIN * HEADD + tid; idx < BJ * HEADD; idx += BJ) {
        Ks[idx] = 0.0f;
        Vs[idx] = 0.0f;
    }
    __syncthreads();

    F4U q[8];
    const float4* qp = (const float4*)(g_q + base + (size_t)rowc * HEADD);
#pragma unroll
    for (int i = 0; i < 8; i++) q[i].f = qp[i];

    u64 O[16];
#pragma unroll
    for (int i = 0; i < 16; i++) O[i] = 0ULL;
    float m = -1e30f, l = 0.0f;

    const unsigned* mrow = g_maskbits + (size_t)(win * LWIN + rowc) * MWPR;
    const float*    brow = g_bias + (size_t)h * BJ * BI + rowc;

    for (int jc = 0; jc < 22; jc++) {            // 22 chunks of 16 keys
        const unsigned w16 =
            (__ldg(mrow + (jc >> 1)) >> ((jc & 1) * 16)) & 0xFFFFu;
        const float* bp = brow + (size_t)(jc * 16) * BI;

        float s[16];
#pragma unroll
        for (int jj = 0; jj < 16; jj++) {
            const F4U* kp = (const F4U*)(Ks + (jc * 16 + jj) * HEADD);
            u64 a0 = 0ULL, a1 = 0ULL;
#pragma unroll
            for (int c4 = 0; c4 < 8; c4 += 2) {
                F4U k0 = kp[c4], k1 = kp[c4 + 1];
                fma2(a0, q[c4].u[0],     k0.u[0]);
                fma2(a0, q[c4].u[1],     k0.u[1]);
                fma2(a1, q[c4 + 1].u[0], k1.u[0]);
                fma2(a1, q[c4 + 1].u[1], k1.u[1]);
            }
            float2 e0 = unpk2(a0), e1 = unpk2(a1);
            float sv = (e0.x + e1.x) + (e0.y + e1.y) + __ldg(bp + (size_t)jj * BI);
            if ((w16 >> jj) & 1u) sv = -1e30f;
            s[jj] = sv;
        }

        float mc = s[0];
#pragma unroll
        for (int jj = 1; jj < 16; jj++) mc = fmaxf(mc, s[jj]);
        if (mc > m) {                           // rescale only when needed
            float scale = __expf(m - mc);
            m = mc;
            l *= scale;
            u64 sc2 = pack2(scale, scale);
#pragma unroll
            for (int i = 0; i < 16; i++) mul2(O[i], sc2);
        }

#pragma unroll
        for (int jj = 0; jj < 16; jj++) {
            float p = __expf(s[jj] - m);
            l += p;
            u64 p2 = pack2(p, p);
            const F4U* vp = (const F4U*)(Vs + (jc * 16 + jj) * HEADD);
#pragma unroll
            for (int c4 = 0; c4 < 8; c4++) {
                F4U v4 = vp[c4];
                fma2(O[c4 * 2],     p2, v4.u[0]);
                fma2(O[c4 * 2 + 1], p2, v4.u[1]);
            }
        }
    }

    const float inv = 1.0f / l;
    float* op = g_ao + ((size_t)(win * LWIN) + rowc) * DIMM + h * HEADD;
#pragma unroll
    for (int i = 0; i < 8; i++) {
        float2 eA = unpk2(O[i * 2]), eB = unpk2(O[i * 2 + 1]);
        *(float4*)(op + i * 4) =
            make_float4(eA.x * inv, eA.y * inv, eB.x * inv, eB.y * inv);
    }
}

extern "C" void kernel_launch(void* const* d_in, const int* in_sizes, int n_in,
                              void* d_out, int out_size)
{
    const float* x       = (const float*)d_in[0];
    const float* qkv_w   = (const float*)d_in[1];
    const float* table   = (const float*)d_in[2];
    const float* proj_w  = (const float*)d_in[3];
    const float* proj_b  = (const float*)d_in[4];
    const void*  mask    = d_in[5];
    const int*   rel_idx = (const int*)d_in[6];
    float*       out     = (float*)d_out;

    detect_mask_kernel<<<1, 32>>>((const unsigned int*)mask);
    convert_mask_kernel<<<(NWIN * LWIN * MWPR + 255) / 256, 256>>>(mask);
    bias_kernel<<<NHEAD * BJ, BI>>>(rel_idx, table);

    const int n4 = MROWS * DIMM / 4;
    split_kernel<<<(n4 + 255) / 256, 256>>>(x, 0);
    tsplit_kernel<<<dim3(3 * DIMM / 32, DIMM / 32), dim3(32, 8)>>>(qkv_w, 0);
    tsplit_kernel<<<dim3(DIMM / 32, DIMM / 32), dim3(32, 8)>>>(proj_w, 1);

    // K1: qkv = x @ qkv_w (bf16x3 wmma, fused scatter)
    cudaFuncSetAttribute(wmma_gemm_kernel, cudaFuncAttributeMaxDynamicSharedMemorySize,
                         WMMA_SMEM_BYTES);
    wmma_gemm_kernel<<<dim3(9, 343), 256, WMMA_SMEM_BYTES>>>(0, nullptr, nullptr);

    // K2: attention
    cudaFuncSetAttribute(attn_kernel, cudaFuncAttributeMaxDynamicSharedMemorySize,
                         ATTN_SMEM_BYTES);
    attn_kernel<<<dim3(NHEAD, NWIN), BJ, ATTN_SMEM_BYTES>>>();

    // K3: out = ao @ proj_w + b (bf16x3 wmma, fused bias)
    split_kernel<<<(n4 + 255) / 256, 256>>>(nullptr, 1);
    wmma_gemm_kernel<<<dim3(3, 343), 256, WMMA_SMEM_BYTES>>>(1, proj_b, out);
}

// round 11
// speedup vs baseline: 1.1532x; 1.1532x over previous
#include <cuda_runtime.h>
#include <cuda_bf16.h>
#include <mma.h>

#define NWIN  64
#define NHEAD 12
#define LWIN  343
#define DIMM  384
#define HEADD 32
#define TBL   2197
#define MROWS (NWIN * LWIN)            // 21952
#define QK_SCALE 0.1767766952966369f   // 32^-0.5
#define MWPR  12
#define BJ    352
#define BI    344
#define NCHUNK 11
#define SPAD  24                       // smem row stride (bf16): 48B (mult of 16B)
#define CPAD  36                       // epilogue f32 stride: 144B (mult of 16B)

typedef unsigned long long u64;
typedef __nv_bfloat16 bf16;
using namespace nvcuda;

// --- device globals: ONLY referenced inside device code, never passed from host ---
__device__ __align__(16) float g_q [NWIN * NHEAD * LWIN * HEADD];
__device__ __align__(16) float g_k [NWIN * NHEAD * LWIN * HEADD];
__device__ __align__(16) float g_v [NWIN * NHEAD * LWIN * HEADD];
__device__ __align__(16) float g_bias[NHEAD * BJ * BI];
__device__ int g_mask_mode;
__device__ unsigned g_maskbits[NWIN * LWIN * MWPR];

__device__ __align__(16) bf16 g_x_hi [MROWS * DIMM];
__device__ __align__(16) bf16 g_x_lo [MROWS * DIMM];
__device__ __align__(16) bf16 g_ao_hi[MROWS * DIMM];
__device__ __align__(16) bf16 g_ao_lo[MROWS * DIMM];
__device__ __align__(16) bf16 g_wq_hi[3 * DIMM * DIMM];   // qkv_w^T  [1152][384]
__device__ __align__(16) bf16 g_wq_lo[3 * DIMM * DIMM];
__device__ __align__(16) bf16 g_wp_hi[DIMM * DIMM];       // proj_w^T [384][384]
__device__ __align__(16) bf16 g_wp_lo[DIMM * DIMM];

union F4U { float4 f; u64 u[2]; };

__device__ __forceinline__ u64 pack2(float a, float b) {
    u64 r; asm("mov.b64 %0,{%1,%2};" : "=l"(r) : "f"(a), "f"(b)); return r;
}
__device__ __forceinline__ float2 unpk2(u64 v) {
    float2 r; asm("mov.b64 {%0,%1},%2;" : "=f"(r.x), "=f"(r.y) : "l"(v)); return r;
}
__device__ __forceinline__ void fma2(u64& d, u64 a, u64 b) {
    asm("fma.rn.f32x2 %0,%1,%2,%0;" : "+l"(d) : "l"(a), "l"(b));
}
__device__ __forceinline__ void mul2(u64& d, u64 s) {
    asm("mul.rn.f32x2 %0,%0,%1;" : "+l"(d) : "l"(s));
}

// ---------------------------------------------------------------------------
// mask detect / bit-pack / bias precompute (proven)
// ---------------------------------------------------------------------------
__global__ void detect_mask_kernel(const unsigned int* __restrict__ m)
{
    if (threadIdx.x == 0) {
        bool sawF32 = false, sawHigh = false;
        for (int i = 0; i < 256; i++) {
            unsigned w = m[i];
            if (w == 0x3F800000u) sawF32 = true;
            else if (w != 0u && w != 1u) sawHigh = true;
        }
        int mode = 1;
        if (sawHigh) mode = 0;
        else if (sawF32) mode = 2;
        g_mask_mode = mode;
    }
}

__global__ __launch_bounds__(256)
void convert_mask_kernel(const void* __restrict__ mraw)
{
    int idx = blockIdx.x * blockDim.x + threadIdx.x;
    if (idx >= NWIN * LWIN * MWPR) return;
    int wi  = idx % MWPR;
    int row = idx / MWPR;
    size_t base = (size_t)(row / LWIN) * LWIN * LWIN + (size_t)(row % LWIN) * LWIN;
    const int mode = g_mask_mode;
    unsigned bits = 0;
    for (int b = 0; b < 32; b++) {
        int j = wi * 32 + b;
        bool mb;
        if (j >= LWIN)          mb = true;
        else if (mode == 0)     mb = ((const unsigned char*)mraw)[base + j] != 0;
        else if (mode == 1)     mb = ((const int*)mraw)[base + j] != 0;
        else                    mb = ((const float*)mraw)[base + j] != 0.0f;
        bits |= (mb ? 1u : 0u) << b;
    }
    g_maskbits[idx] = bits;
}

__global__ __launch_bounds__(BI)
void bias_kernel(const int* __restrict__ rel_idx, const float* __restrict__ table)
{
    int h = blockIdx.x / BJ, j = blockIdx.x % BJ;
    int i = threadIdx.x;
    float v = 0.0f;
    if (j < LWIN && i < LWIN)
        v = __ldg(table + (size_t)__ldg(rel_idx + (size_t)i * LWIN + j) * NHEAD + h);
    g_bias[((size_t)h * BJ + j) * BI + i] = v;
}

// ---------------------------------------------------------------------------
// hi/lo split of x -> g_x_* (vectorized by 4)
// ---------------------------------------------------------------------------
__global__ __launch_bounds__(256)
void split_kernel(const float* __restrict__ in)
{
    const int n4 = MROWS * DIMM / 4;
    int i = blockIdx.x * 256 + threadIdx.x;
    if (i >= n4) return;
    float4 v = ((const float4*)in)[i];
    bf16 h0 = __float2bfloat16(v.x), h1 = __float2bfloat16(v.y);
    bf16 h2 = __float2bfloat16(v.z), h3 = __float2bfloat16(v.w);
    bf16 l0 = __float2bfloat16(v.x - __bfloat162float(h0));
    bf16 l1 = __float2bfloat16(v.y - __bfloat162float(h1));
    bf16 l2 = __float2bfloat16(v.z - __bfloat162float(h2));
    bf16 l3 = __float2bfloat16(v.w - __bfloat162float(h3));
    ((__nv_bfloat162*)g_x_hi)[i * 2]     = __nv_bfloat162(h0, h1);
    ((__nv_bfloat162*)g_x_hi)[i * 2 + 1] = __nv_bfloat162(h2, h3);
    ((__nv_bfloat162*)g_x_lo)[i * 2]     = __nv_bfloat162(l0, l1);
    ((__nv_bfloat162*)g_x_lo)[i * 2 + 1] = __nv_bfloat162(l2, l3);
}

// transpose+split weights: in[K=384][N] -> (g_wq_*|g_wp_*)[N][384]. mode 0: qkv, 1: proj.
__global__ __launch_bounds__(256)
void tsplit_kernel(const float* __restrict__ in, int mode)
{
    __shared__ float tile[32][33];
    const int N = mode ? DIMM : 3 * DIMM;
    bf16* hi = mode ? g_wp_hi : g_wq_hi;
    bf16* lo = mode ? g_wp_lo : g_wq_lo;
    int n0 = blockIdx.x * 32, k0 = blockIdx.y * 32;
    int tx = threadIdx.x, ty = threadIdx.y;
#pragma unroll
    for (int i = 0; i < 32; i += 8)
        tile[ty + i][tx] = in[(size_t)(k0 + ty + i) * N + n0 + tx];
    __syncthreads();
#pragma unroll
    for (int i = 0; i < 32; i += 8) {
        float v = tile[tx][ty + i];
        bf16 h = __float2bfloat16(v);
        bf16 l = __float2bfloat16(v - __bfloat162float(h));
        size_t o = (size_t)(n0 + ty + i) * DIMM + k0 + tx;
        hi[o] = h; lo[o] = l;
    }
}

// ---------------------------------------------------------------------------
// bf16x3 WMMA GEMM with fused epilogue (CPAD stride legal: 144B mult of 16B).
// mode 0: x @ wq^T (N=1152), scatter into g_q/g_k/g_v (Q pre-scaled)
// mode 1: ao @ wp^T (N=384), + proj_b -> out
// ---------------------------------------------------------------------------
#define WMMA_SMEM_BYTES (8 * 32 * CPAD * 4)   // 36864

__global__ __launch_bounds__(256)
void wmma_gemm_kernel(int mode, const float* __restrict__ pb,
                      float* __restrict__ out)
{
    extern __shared__ __align__(16) char dsm[];
    bf16* AsH = (bf16*)dsm;                  // 64*SPAD
    bf16* AsL = AsH + 64 * SPAD;
    bf16* BsH = AsL + 64 * SPAD;             // 128*SPAD
    bf16* BsL = BsH + 128 * SPAD;
    float* Cs = (float*)dsm;                 // reused after mainloop: 8*32*CPAD

    const bf16* Ahi = mode ? g_ao_hi : g_x_hi;
    const bf16* Alo = mode ? g_ao_lo : g_x_lo;
    const bf16* Bhi = mode ? g_wp_hi : g_wq_hi;
    const bf16* Blo = mode ? g_wp_lo : g_wq_lo;

    const int m0 = blockIdx.y * 64, n0 = blockIdx.x * 128;
    const int tid = threadIdx.x;
    const int lane = tid & 31, w = tid >> 5;
    const int wm = w >> 2, wn = w & 3;
    const int srow = tid >> 1, shalf = tid & 1;

    wmma::fragment<wmma::accumulator, 16, 16, 16, float> c[2][2];
#pragma unroll
    for (int i = 0; i < 2; i++)
#pragma unroll
        for (int j = 0; j < 2; j++) wmma::fill_fragment(c[i][j], 0.0f);

    for (int k0 = 0; k0 < DIMM; k0 += 16) {
        if (tid < 128) {
            size_t go = (size_t)(m0 + srow) * DIMM + k0 + shalf * 8;
            *(uint4*)&AsH[srow * SPAD + shalf * 8] = *(const uint4*)&Ahi[go];
            *(uint4*)&AsL[srow * SPAD + shalf * 8] = *(const uint4*)&Alo[go];
        }
        {
            size_t go = (size_t)(n0 + srow) * DIMM + k0 + shalf * 8;
            *(uint4*)&BsH[srow * SPAD + shalf * 8] = *(const uint4*)&Bhi[go];
            *(uint4*)&BsL[srow * SPAD + shalf * 8] = *(const uint4*)&Blo[go];
        }
        __syncthreads();

        wmma::fragment<wmma::matrix_a, 16, 16, 16, bf16, wmma::row_major> aH[2], aL[2];
        wmma::fragment<wmma::matrix_b, 16, 16, 16, bf16, wmma::col_major> bH[2], bL[2];
#pragma unroll
        for (int i = 0; i < 2; i++) {
            wmma::load_matrix_sync(aH[i], &AsH[(wm * 32 + i * 16) * SPAD], SPAD);
            wmma::load_matrix_sync(aL[i], &AsL[(wm * 32 + i * 16) * SPAD], SPAD);
        }
#pragma unroll
        for (int j = 0; j < 2; j++) {
            wmma::load_matrix_sync(bH[j], &BsH[(wn * 32 + j * 16) * SPAD], SPAD);
            wmma::load_matrix_sync(bL[j], &BsL[(wn * 32 + j * 16) * SPAD], SPAD);
        }
#pragma unroll
        for (int i = 0; i < 2; i++)
#pragma unroll
            for (int j = 0; j < 2; j++) {
                wmma::mma_sync(c[i][j], aH[i], bH[j], c[i][j]);
                wmma::mma_sync(c[i][j], aH[i], bL[j], c[i][j]);
                wmma::mma_sync(c[i][j], aL[i], bH[j], c[i][j]);
            }
        __syncthreads();
    }

    // epilogue: fragments -> Cs (per-warp 32xCPAD tile) -> fused writeout
    float* ct = Cs + w * (32 * CPAD);
#pragma unroll
    for (int i = 0; i < 2; i++)
#pragma unroll
        for (int j = 0; j < 2; j++)
            wmma::store_matrix_sync(ct + i * 16 * CPAD + j * 16, c[i][j], CPAD,
                                    wmma::mem_row_major);
    __syncwarp();

    const int colbase = n0 + wn * 32;     // multiple of 32 -> head aligned
    if (mode == 0) {
        const int three = colbase / DIMM;
        const int cm = colbase - three * DIMM;
        const int h = cm >> 5;
        float* dst = (three == 0) ? g_q : (three == 1 ? g_k : g_v);
        const float sc = (three == 0) ? QK_SCALE : 1.0f;
#pragma unroll 4
        for (int r = 0; r < 32; r++) {
            int mg = m0 + wm * 32 + r;
            int n = mg / LWIN, l = mg - n * LWIN;
            dst[(size_t)((n * NHEAD + h) * LWIN + l) * HEADD + lane] =
                ct[r * CPAD + lane] * sc;
        }
    } else {
        const float bv = pb[colbase + lane];
#pragma unroll 4
        for (int r = 0; r < 32; r++) {
            int mg = m0 + wm * 32 + r;
            out[(size_t)mg * DIMM + colbase + lane] = ct[r * CPAD + lane] + bv;
        }
    }
}

// ---------------------------------------------------------------------------
// K2: flash attention — EXACT R6-proven config (chunk=32, no reg cap),
// with fused bf16 hi/lo output split. grid(12,64), 352 thr.
// ---------------------------------------------------------------------------
#define ATTN_SMEM_BYTES (BJ * HEADD * 2 * 4)   // 90112

__global__ __launch_bounds__(BJ, 1)
void attn_kernel()
{
    extern __shared__ float smem[];
    float* Ks = smem;
    float* Vs = smem + BJ * HEADD;

    const int h   = blockIdx.x;
    const int win = blockIdx.y;
    const int tid = threadIdx.x;
    const int rowc = (tid < LWIN) ? tid : (LWIN - 1);
    const size_t base = (size_t)(win * NHEAD + h) * LWIN * HEADD;

    for (int idx = tid; idx < LWIN * HEADD; idx += BJ) {
        Ks[idx] = g_k[base + idx];
        Vs[idx] = g_v[base + idx];
    }
    for (int idx = LWIN * HEADD + tid; idx < BJ * HEADD; idx += BJ) {
        Ks[idx] = 0.0f;
        Vs[idx] = 0.0f;
    }
    __syncthreads();

    F4U q[8];
    const float4* qp = (const float4*)(g_q + base + (size_t)rowc * HEADD);
#pragma unroll
    for (int i = 0; i < 8; i++) q[i].f = qp[i];

    u64 O[16];
#pragma unroll
    for (int i = 0; i < 16; i++) O[i] = 0ULL;
    float m = -1e30f, l = 0.0f;

    const unsigned* mrow = g_maskbits + (size_t)(win * LWIN + rowc) * MWPR;
    const float*    brow = g_bias + (size_t)h * BJ * BI + rowc;

    for (int jc = 0; jc < NCHUNK; jc++) {
        const unsigned mw = __ldg(mrow + jc);
        const float*   bp = brow + (size_t)(jc * 32) * BI;

        float s[32];
#pragma unroll
        for (int jj = 0; jj < 32; jj++) {
            const F4U* kp = (const F4U*)(Ks + (jc * 32 + jj) * HEADD);
            u64 a0 = 0ULL, a1 = 0ULL;
#pragma unroll
            for (int c4 = 0; c4 < 8; c4 += 2) {
                F4U k0 = kp[c4], k1 = kp[c4 + 1];
                fma2(a0, q[c4].u[0],     k0.u[0]);
                fma2(a0, q[c4].u[1],     k0.u[1]);
                fma2(a1, q[c4 + 1].u[0], k1.u[0]);
                fma2(a1, q[c4 + 1].u[1], k1.u[1]);
            }
            float2 e0 = unpk2(a0), e1 = unpk2(a1);
            float sv = (e0.x + e1.x) + (e0.y + e1.y) + __ldg(bp + (size_t)jj * BI);
            if ((mw >> jj) & 1u) sv = -1e30f;
            s[jj] = sv;
        }

        float mc = s[0];
#pragma unroll
        for (int jj = 1; jj < 32; jj++) mc = fmaxf(mc, s[jj]);
        float mn = fmaxf(m, mc);
        float scale = __expf(m - mn);
        m = mn;
        l *= scale;
        u64 sc2 = pack2(scale, scale);
#pragma unroll
        for (int i = 0; i < 16; i++) mul2(O[i], sc2);

#pragma unroll
        for (int jj = 0; jj < 32; jj++) {
            float p = __expf(s[jj] - m);
            l += p;
            u64 p2 = pack2(p, p);
            const F4U* vp = (const F4U*)(Vs + (jc * 32 + jj) * HEADD);
#pragma unroll
            for (int c4 = 0; c4 < 8; c4++) {
                F4U v4 = vp[c4];
                fma2(O[c4 * 2],     p2, v4.u[0]);
                fma2(O[c4 * 2 + 1], p2, v4.u[1]);
            }
        }
    }

    // fused epilogue: normalize + bf16 hi/lo split -> g_ao_hi / g_ao_lo
    const float inv = 1.0f / l;
    const size_t rb = ((size_t)(win * LWIN) + rowc) * DIMM + h * HEADD;
#pragma unroll
    for (int i = 0; i < 8; i++) {
        float2 eA = unpk2(O[i * 2]), eB = unpk2(O[i * 2 + 1]);
        float o0 = eA.x * inv, o1 = eA.y * inv, o2 = eB.x * inv, o3 = eB.y * inv;
        bf16 h0 = __float2bfloat16(o0), h1 = __float2bfloat16(o1);
        bf16 h2 = __float2bfloat16(o2), h3 = __float2bfloat16(o3);
        bf16 l0 = __float2bfloat16(o0 - __bfloat162float(h0));
        bf16 l1 = __float2bfloat16(o1 - __bfloat162float(h1));
        bf16 l2 = __float2bfloat16(o2 - __bfloat162float(h2));
        bf16 l3 = __float2bfloat16(o3 - __bfloat162float(h3));
        __nv_bfloat162* ph = (__nv_bfloat162*)(g_ao_hi + rb + i * 4);
        __nv_bfloat162* pl = (__nv_bfloat162*)(g_ao_lo + rb + i * 4);
        ph[0] = __nv_bfloat162(h0, h1); ph[1] = __nv_bfloat162(h2, h3);
        pl[0] = __nv_bfloat162(l0, l1); pl[1] = __nv_bfloat162(l2, l3);
    }
}

extern "C" void kernel_launch(void* const* d_in, const int* in_sizes, int n_in,
                              void* d_out, int out_size)
{
    const float* x       = (const float*)d_in[0];
    const float* qkv_w   = (const float*)d_in[1];
    const float* table   = (const float*)d_in[2];
    const float* proj_w  = (const float*)d_in[3];
    const float* proj_b  = (const float*)d_in[4];
    const void*  mask    = d_in[5];
    const int*   rel_idx = (const int*)d_in[6];
    float*       out     = (float*)d_out;

    detect_mask_kernel<<<1, 32>>>((const unsigned int*)mask);
    convert_mask_kernel<<<(NWIN * LWIN * MWPR + 255) / 256, 256>>>(mask);
    bias_kernel<<<NHEAD * BJ, BI>>>(rel_idx, table);

    const int n4 = MROWS * DIMM / 4;
    split_kernel<<<(n4 + 255) / 256, 256>>>(x);
    tsplit_kernel<<<dim3(3 * DIMM / 32, DIMM / 32), dim3(32, 8)>>>(qkv_w, 0);
    tsplit_kernel<<<dim3(DIMM / 32, DIMM / 32), dim3(32, 8)>>>(proj_w, 1);

    // K1: qkv = x @ qkv_w (bf16x3 wmma, fused scatter)
    cudaFuncSetAttribute(wmma_gemm_kernel, cudaFuncAttributeMaxDynamicSharedMemorySize,
                         WMMA_SMEM_BYTES);
    wmma_gemm_kernel<<<dim3(9, 343), 256, WMMA_SMEM_BYTES>>>(0, nullptr, nullptr);

    // K2: attention (writes g_ao_hi/lo directly)
    cudaFuncSetAttribute(attn_kernel, cudaFuncAttributeMaxDynamicSharedMemorySize,
                         ATTN_SMEM_BYTES);
    attn_kernel<<<dim3(NHEAD, NWIN), BJ, ATTN_SMEM_BYTES>>>();

    // K3: out = ao @ proj_w + b (bf16x3 wmma, fused bias)
    wmma_gemm_kernel<<<dim3(3, 343), 256, WMMA_SMEM_BYTES>>>(1, proj_b, out);
}

// round 14
// speedup vs baseline: 1.2069x; 1.0466x over previous
#include <cuda_runtime.h>
#include <cuda_bf16.h>
#include <mma.h>
#include <cstdint>

#define NWIN  64
#define NHEAD 12
#define LWIN  343
#define DIMM  384
#define HEADD 32
#define TBL   2197
#define MROWS (NWIN * LWIN)            // 21952
#define QK_SCALE 0.1767766952966369f   // 32^-0.5
#define MWPR  12
#define BJ    352
#define BI    344
#define NCHUNK 11
#define CPAD  36                       // epilogue f32 stride: 144B (mult of 16B)
#define KSTEP 32
#define LDB   40                       // smem row stride (bf16): 80B, conflict-free + 16B-mult

typedef unsigned long long u64;
typedef __nv_bfloat16 bf16;
using namespace nvcuda;

// --- device globals: ONLY referenced inside device code, never passed from host ---
__device__ __align__(16) float g_q [NWIN * NHEAD * LWIN * HEADD];
__device__ __align__(16) float g_k [NWIN * NHEAD * LWIN * HEADD];
__device__ __align__(16) float g_v [NWIN * NHEAD * LWIN * HEADD];
__device__ __align__(16) float g_bias[NHEAD * BJ * BI];
__device__ unsigned g_maskbits[NWIN * LWIN * MWPR];

__device__ __align__(16) bf16 g_x_hi [MROWS * DIMM];
__device__ __align__(16) bf16 g_x_lo [MROWS * DIMM];
__device__ __align__(16) bf16 g_ao_hi[MROWS * DIMM];
__device__ __align__(16) bf16 g_ao_lo[MROWS * DIMM];
__device__ __align__(16) bf16 g_wq_hi[3 * DIMM * DIMM];   // qkv_w^T  [1152][384]
__device__ __align__(16) bf16 g_wq_lo[3 * DIMM * DIMM];
__device__ __align__(16) bf16 g_wp_hi[DIMM * DIMM];       // proj_w^T [384][384]
__device__ __align__(16) bf16 g_wp_lo[DIMM * DIMM];

union F4U { float4 f; u64 u[2]; };

__device__ __forceinline__ u64 pack2(float a, float b) {
    u64 r; asm("mov.b64 %0,{%1,%2};" : "=l"(r) : "f"(a), "f"(b)); return r;
}
__device__ __forceinline__ float2 unpk2(u64 v) {
    float2 r; asm("mov.b64 {%0,%1},%2;" : "=f"(r.x), "=f"(r.y) : "l"(v)); return r;
}
__device__ __forceinline__ void fma2(u64& d, u64 a, u64 b) {
    asm("fma.rn.f32x2 %0,%1,%2,%0;" : "+l"(d) : "l"(a), "l"(b));
}
__device__ __forceinline__ void mul2(u64& d, u64 s) {
    asm("mul.rn.f32x2 %0,%0,%1;" : "+l"(d) : "l"(s));
}

// ---------------------------------------------------------------------------
// K1: mask bit-pack with inline dtype detection (smem broadcast per block).
// ---------------------------------------------------------------------------
__global__ __launch_bounds__(256)
void convert_mask_kernel(const void* __restrict__ mraw)
{
    __shared__ int smode;
    if (threadIdx.x == 0) {
        const unsigned* mm = (const unsigned*)mraw;
        bool sawF32 = false, sawHigh = false;
        for (int i = 0; i < 256; i++) {
            unsigned w = mm[i];
            if (w == 0x3F800000u) sawF32 = true;
            else if (w != 0u && w != 1u) sawHigh = true;
        }
        smode = sawHigh ? 0 : (sawF32 ? 2 : 1);
    }
    __syncthreads();
    const int mode = smode;

    int idx = blockIdx.x * blockDim.x + threadIdx.x;
    if (idx >= NWIN * LWIN * MWPR) return;
    int wi  = idx % MWPR;
    int row = idx / MWPR;
    size_t base = (size_t)(row / LWIN) * LWIN * LWIN + (size_t)(row % LWIN) * LWIN;
    unsigned bits = 0;
    for (int b = 0; b < 32; b++) {
        int j = wi * 32 + b;
        bool mb;
        if (j >= LWIN)          mb = true;
        else if (mode == 0)     mb = ((const unsigned char*)mraw)[base + j] != 0;
        else if (mode == 1)     mb = ((const int*)mraw)[base + j] != 0;
        else                    mb = ((const float*)mraw)[base + j] != 0.0f;
        bits |= (mb ? 1u : 0u) << b;
    }
    g_maskbits[idx] = bits;
}

__global__ __launch_bounds__(BI)
void bias_kernel(const int* __restrict__ rel_idx, const float* __restrict__ table)
{
    int h = blockIdx.x / BJ, j = blockIdx.x % BJ;
    int i = threadIdx.x;
    float v = 0.0f;
    if (j < LWIN && i < LWIN)
        v = __ldg(table + (size_t)__ldg(rel_idx + (size_t)i * LWIN + j) * NHEAD + h);
    g_bias[((size_t)h * BJ + j) * BI + i] = v;
}

// ---------------------------------------------------------------------------
// hi/lo split of x -> g_x_* (vectorized by 4)
// ---------------------------------------------------------------------------
__global__ __launch_bounds__(256)
void split_kernel(const float* __restrict__ in)
{
    const int n4 = MROWS * DIMM / 4;
    int i = blockIdx.x * 256 + threadIdx.x;
    if (i >= n4) return;
    float4 v = ((const float4*)in)[i];
    bf16 h0 = __float2bfloat16(v.x), h1 = __float2bfloat16(v.y);
    bf16 h2 = __float2bfloat16(v.z), h3 = __float2bfloat16(v.w);
    bf16 l0 = __float2bfloat16(v.x - __bfloat162float(h0));
    bf16 l1 = __float2bfloat16(v.y - __bfloat162float(h1));
    bf16 l2 = __float2bfloat16(v.z - __bfloat162float(h2));
    bf16 l3 = __float2bfloat16(v.w - __bfloat162float(h3));
    ((__nv_bfloat162*)g_x_hi)[i * 2]     = __nv_bfloat162(h0, h1);
    ((__nv_bfloat162*)g_x_hi)[i * 2 + 1] = __nv_bfloat162(h2, h3);
    ((__nv_bfloat162*)g_x_lo)[i * 2]     = __nv_bfloat162(l0, l1);
    ((__nv_bfloat162*)g_x_lo)[i * 2 + 1] = __nv_bfloat162(l2, l3);
}

// combined transpose+split of both weights: blockIdx.x < 36 -> qkv, else proj.
__global__ __launch_bounds__(256)
void tsplit_kernel(const float* __restrict__ wq, const float* __restrict__ wp)
{
    __shared__ float tile[32][33];
    const int mode = (blockIdx.x >= 36) ? 1 : 0;
    const int bx   = mode ? (blockIdx.x - 36) : blockIdx.x;
    const float* in = mode ? wp : wq;
    const int N = mode ? DIMM : 3 * DIMM;
    bf16* hi = mode ? g_wp_hi : g_wq_hi;
    bf16* lo = mode ? g_wp_lo : g_wq_lo;
    int n0 = bx * 32, k0 = blockIdx.y * 32;
    int tx = threadIdx.x, ty = threadIdx.y;
#pragma unroll
    for (int i = 0; i < 32; i += 8)
        tile[ty + i][tx] = in[(size_t)(k0 + ty + i) * N + n0 + tx];
    __syncthreads();
#pragma unroll
    for (int i = 0; i < 32; i += 8) {
        float v = tile[tx][ty + i];
        bf16 h = __float2bfloat16(v);
        bf16 l = __float2bfloat16(v - __bfloat162float(h));
        size_t o = (size_t)(n0 + ty + i) * DIMM + k0 + tx;
        hi[o] = h; lo[o] = l;
    }
}

// ---------------------------------------------------------------------------
// bf16x3 WMMA GEMM, double-buffered k-step 32, fused epilogues.
// mode 0: x @ wq^T (N=1152) -> scatter g_q/g_k/g_v (Q pre-scaled)
// mode 1: ao @ wp^T (N=384) -> + proj_b -> out
// Block 64x128, 256 thr (8 warps, warp tile 32x32).
// smem: 2 stages x (64+128+... rows) x LDB bf16 = 61,440 B; epilogue reuses it.
// ---------------------------------------------------------------------------
#define STAGE_BF16 (384 * LDB)                 // 15360 bf16 = 30720 B per stage
#define GEMM_SMEM  (2 * STAGE_BF16 * 2)        // 61440 B

__global__ __launch_bounds__(256)
void wmma_gemm_kernel(int mode, const float* __restrict__ pb,
                      float* __restrict__ out)
{
    extern __shared__ __align__(16) bf16 sm[];
    float* Cs = (float*)sm;                    // epilogue reuse (36,864 B)

    const bf16* Ahi = mode ? g_ao_hi : g_x_hi;
    const bf16* Alo = mode ? g_ao_lo : g_x_lo;
    const bf16* Bhi = mode ? g_wp_hi : g_wq_hi;
    const bf16* Blo = mode ? g_wp_lo : g_wq_lo;

    const int m0 = blockIdx.y * 64, n0 = blockIdx.x * 128;
    const int tid = threadIdx.x;
    const int lane = tid & 31, w = tid >> 5;
    const int wm = w >> 2, wn = w & 3;

    wmma::fragment<wmma::accumulator, 16, 16, 16, float> c[2][2];
#pragma unroll
    for (int i = 0; i < 2; i++)
#pragma unroll
        for (int j = 0; j < 2; j++) wmma::fill_fragment(c[i][j], 0.0f);

    // stage layout (bf16 offsets within stage): AH 0, AL 2560, BH 5120, BL 10240
    auto load_stage = [&](int s, int kc) {
        bf16* AH = sm + s * STAGE_BF16;
        bf16* AL = AH + 2560;
        bf16* BH = AH + 5120;
        bf16* BL = AH + 10240;
        {
            int row = tid >> 2, c8 = (tid & 3) << 3;
            size_t g = (size_t)(m0 + row) * DIMM + kc + c8;
            *(uint4*)&AH[row * LDB + c8] = *(const uint4*)&Ahi[g];
            *(uint4*)&AL[row * LDB + c8] = *(const uint4*)&Alo[g];
        }
#pragma unroll
        for (int u = 0; u < 2; u++) {
            int e = tid + u * 256;
            int row = e >> 2, c8 = (e & 3) << 3;
            size_t g = (size_t)(n0 + row) * DIMM + kc + c8;
            *(uint4*)&BH[row * LDB + c8] = *(const uint4*)&Bhi[g];
            *(uint4*)&BL[row * LDB + c8] = *(const uint4*)&Blo[g];
        }
    };

    load_stage(0, 0);
    __syncthreads();

    for (int it = 0; it < DIMM / KSTEP; it++) {         // 12 iterations
        const int cur = it & 1;
        if (it < DIMM / KSTEP - 1) load_stage(cur ^ 1, (it + 1) * KSTEP);

        bf16* AH = sm + cur * STAGE_BF16;
        bf16* AL = AH + 2560;
        bf16* BH = AH + 5120;
        bf16* BL = AH + 10240;

#pragma unroll
        for (int ks = 0; ks < 2; ks++) {
            const int ko = ks * 16;
            wmma::fragment<wmma::matrix_a, 16, 16, 16, bf16, wmma::row_major> aH[2], aL[2];
            wmma::fragment<wmma::matrix_b, 16, 16, 16, bf16, wmma::col_major> bH[2], bL[2];
#pragma unroll
            for (int i = 0; i < 2; i++) {
                wmma::load_matrix_sync(aH[i], &AH[(wm * 32 + i * 16) * LDB + ko], LDB);
                wmma::load_matrix_sync(aL[i], &AL[(wm * 32 + i * 16) * LDB + ko], LDB);
            }
#pragma unroll
            for (int j = 0; j < 2; j++) {
                wmma::load_matrix_sync(bH[j], &BH[(wn * 32 + j * 16) * LDB + ko], LDB);
                wmma::load_matrix_sync(bL[j], &BL[(wn * 32 + j * 16) * LDB + ko], LDB);
            }
#pragma unroll
            for (int i = 0; i < 2; i++)
#pragma unroll
                for (int j = 0; j < 2; j++) {
                    wmma::mma_sync(c[i][j], aH[i], bH[j], c[i][j]);
                    wmma::mma_sync(c[i][j], aH[i], bL[j], c[i][j]);
                    wmma::mma_sync(c[i][j], aL[i], bH[j], c[i][j]);
                }
        }
        __syncthreads();
    }

    // epilogue: fragments -> Cs (per-warp 32xCPAD tile) -> fused writeout
    float* ct = Cs + w * (32 * CPAD);
#pragma unroll
    for (int i = 0; i < 2; i++)
#pragma unroll
        for (int j = 0; j < 2; j++)
            wmma::store_matrix_sync(ct + i * 16 * CPAD + j * 16, c[i][j], CPAD,
                                    wmma::mem_row_major);
    __syncwarp();

    const int colbase = n0 + wn * 32;     // multiple of 32 -> head aligned
    if (mode == 0) {
        const int three = colbase / DIMM;
        const int cm = colbase - three * DIMM;
        const int h = cm >> 5;
        float* dst = (three == 0) ? g_q : (three == 1 ? g_k : g_v);
        const float sc = (three == 0) ? QK_SCALE : 1.0f;
#pragma unroll 4
        for (int r = 0; r < 32; r++) {
            int mg = m0 + wm * 32 + r;
            int n = mg / LWIN, l = mg - n * LWIN;
            dst[(size_t)((n * NHEAD + h) * LWIN + l) * HEADD + lane] =
                ct[r * CPAD + lane] * sc;
        }
    } else {
        const float bv = pb[colbase + lane];
#pragma unroll 4
        for (int r = 0; r < 32; r++) {
            int mg = m0 + wm * 32 + r;
            out[(size_t)mg * DIMM + colbase + lane] = ct[r * CPAD + lane] + bv;
        }
    }
}

// ---------------------------------------------------------------------------
// K2: flash attention — unchanged R10 (proven), fused ao hi/lo split.
// ---------------------------------------------------------------------------
#define ATTN_SMEM_BYTES (BJ * HEADD * 2 * 4)   // 90112

__global__ __launch_bounds__(BJ, 1)
void attn_kernel()
{
    extern __shared__ float smem[];
    float* Ks = smem;
    float* Vs = smem + BJ * HEADD;

    const int h   = blockIdx.x;
    const int win = blockIdx.y;
    const int tid = threadIdx.x;
    const int rowc = (tid < LWIN) ? tid : (LWIN - 1);
    const size_t base = (size_t)(win * NHEAD + h) * LWIN * HEADD;

    for (int idx = tid; idx < LWIN * HEADD; idx += BJ) {
        Ks[idx] = g_k[base + idx];
        Vs[idx] = g_v[base + idx];
    }
    for (int idx = LWIN * HEADD + tid; idx < BJ * HEADD; idx += BJ) {
        Ks[idx] = 0.0f;
        Vs[idx] = 0.0f;
    }
    __syncthreads();

    F4U q[8];
    const float4* qp = (const float4*)(g_q + base + (size_t)rowc * HEADD);
#pragma unroll
    for (int i = 0; i < 8; i++) q[i].f = qp[i];

    u64 O[16];
#pragma unroll
    for (int i = 0; i < 16; i++) O[i] = 0ULL;
    float m = -1e30f, l = 0.0f;

    const unsigned* mrow = g_maskbits + (size_t)(win * LWIN + rowc) * MWPR;
    const float*    brow = g_bias + (size_t)h * BJ * BI + rowc;

    for (int jc = 0; jc < NCHUNK; jc++) {
        const unsigned mw = __ldg(mrow + jc);
        const float*   bp = brow + (size_t)(jc * 32) * BI;

        float s[32];
#pragma unroll
        for (int jj = 0; jj < 32; jj++) {
            const F4U* kp = (const F4U*)(Ks + (jc * 32 + jj) * HEADD);
            u64 a0 = 0ULL, a1 = 0ULL;
#pragma unroll
            for (int c4 = 0; c4 < 8; c4 += 2) {
                F4U k0 = kp[c4], k1 = kp[c4 + 1];
                fma2(a0, q[c4].u[0],     k0.u[0]);
                fma2(a0, q[c4].u[1],     k0.u[1]);
                fma2(a1, q[c4 + 1].u[0], k1.u[0]);
                fma2(a1, q[c4 + 1].u[1], k1.u[1]);
            }
            float2 e0 = unpk2(a0), e1 = unpk2(a1);
            float sv = (e0.x + e1.x) + (e0.y + e1.y) + __ldg(bp + (size_t)jj * BI);
            if ((mw >> jj) & 1u) sv = -1e30f;
            s[jj] = sv;
        }

        float mc = s[0];
#pragma unroll
        for (int jj = 1; jj < 32; jj++) mc = fmaxf(mc, s[jj]);
        float mn = fmaxf(m, mc);
        float scale = __expf(m - mn);
        m = mn;
        l *= scale;
        u64 sc2 = pack2(scale, scale);
#pragma unroll
        for (int i = 0; i < 16; i++) mul2(O[i], sc2);

#pragma unroll
        for (int jj = 0; jj < 32; jj++) {
            float p = __expf(s[jj] - m);
            l += p;
            u64 p2 = pack2(p, p);
            const F4U* vp = (const F4U*)(Vs + (jc * 32 + jj) * HEADD);
#pragma unroll
            for (int c4 = 0; c4 < 8; c4++) {
                F4U v4 = vp[c4];
                fma2(O[c4 * 2],     p2, v4.u[0]);
                fma2(O[c4 * 2 + 1], p2, v4.u[1]);
            }
        }
    }

    // fused epilogue: normalize + bf16 hi/lo split -> g_ao_hi / g_ao_lo
    const float inv = 1.0f / l;
    const size_t rb = ((size_t)(win * LWIN) + rowc) * DIMM + h * HEADD;
#pragma unroll
    for (int i = 0; i < 8; i++) {
        float2 eA = unpk2(O[i * 2]), eB = unpk2(O[i * 2 + 1]);
        float o0 = eA.x * inv, o1 = eA.y * inv, o2 = eB.x * inv, o3 = eB.y * inv;
        bf16 h0 = __float2bfloat16(o0), h1 = __float2bfloat16(o1);
        bf16 h2 = __float2bfloat16(o2), h3 = __float2bfloat16(o3);
        bf16 l0 = __float2bfloat16(o0 - __bfloat162float(h0));
        bf16 l1 = __float2bfloat16(o1 - __bfloat162float(h1));
        bf16 l2 = __float2bfloat16(o2 - __bfloat162float(h2));
        bf16 l3 = __float2bfloat16(o3 - __bfloat162float(h3));
        __nv_bfloat162* ph = (__nv_bfloat162*)(g_ao_hi + rb + i * 4);
        __nv_bfloat162* pl = (__nv_bfloat162*)(g_ao_lo + rb + i * 4);
        ph[0] = __nv_bfloat162(h0, h1); ph[1] = __nv_bfloat162(h2, h3);
        pl[0] = __nv_bfloat162(l0, l1); pl[1] = __nv_bfloat162(l2, l3);
    }
}

extern "C" void kernel_launch(void* const* d_in, const int* in_sizes, int n_in,
                              void* d_out, int out_size)
{
    const float* x       = (const float*)d_in[0];
    const float* qkv_w   = (const float*)d_in[1];
    const float* table   = (const float*)d_in[2];
    const float* proj_w  = (const float*)d_in[3];
    const float* proj_b  = (const float*)d_in[4];
    const void*  mask    = d_in[5];
    const int*   rel_idx = (const int*)d_in[6];
    float*       out     = (float*)d_out;

    // launch order chosen so ncu (-s 5 -c 1) profiles attn_kernel (#6)
    convert_mask_kernel<<<(NWIN * LWIN * MWPR + 255) / 256, 256>>>(mask);    // 1
    bias_kernel<<<NHEAD * BJ, BI>>>(rel_idx, table);                         // 2
    const int n4 = MROWS * DIMM / 4;
    split_kernel<<<(n4 + 255) / 256, 256>>>(x);                              // 3
    tsplit_kernel<<<dim3(48, 12), dim3(32, 8)>>>(qkv_w, proj_w);             // 4

    cudaFuncSetAttribute(wmma_gemm_kernel, cudaFuncAttributeMaxDynamicSharedMemorySize,
                         GEMM_SMEM);
    wmma_gemm_kernel<<<dim3(9, 343), 256, GEMM_SMEM>>>(0, nullptr, nullptr); // 5 (qkv)

    cudaFuncSetAttribute(attn_kernel, cudaFuncAttributeMaxDynamicSharedMemorySize,
                         ATTN_SMEM_BYTES);
    attn_kernel<<<dim3(NHEAD, NWIN), BJ, ATTN_SMEM_BYTES>>>();               // 6 (profiled)

    wmma_gemm_kernel<<<dim3(3, 343), 256, GEMM_SMEM>>>(1, proj_b, out);      // 7 (proj)
}

// round 15
// speedup vs baseline: 1.5860x; 1.3141x over previous
#include <cuda_runtime.h>
#include <cuda_fp16.h>
#include <mma.h>
#include <cstdint>

#define NWIN  64
#define NHEAD 12
#define LWIN  343
#define DIMM  384
#define HEADD 32
#define TBL   2197
#define MROWS (NWIN * LWIN)            // 21952
#define QK_SCALE 0.1767766952966369f   // 32^-0.5
#define MWPR  12
#define BJ    352
#define BI    344
#define NCHUNK 11
#define CPAD  36                       // epilogue f32 stride: 144B (mult of 16B)
#define KSTEP 32
#define LDB   40                       // smem row stride (half): 80B, conflict-free + 16B-mult

typedef unsigned long long u64;

using namespace nvcuda;

// --- device globals: ONLY referenced inside device code, never passed from host ---
__device__ __align__(16) float g_q [NWIN * NHEAD * LWIN * HEADD];
__device__ __align__(16) float g_k [NWIN * NHEAD * LWIN * HEADD];
__device__ __align__(16) float g_v [NWIN * NHEAD * LWIN * HEADD];
__device__ __align__(16) float g_bias[NHEAD * BJ * BI];
__device__ unsigned g_maskbits[NWIN * LWIN * MWPR];

__device__ __align__(16) __half g_x_h [MROWS * DIMM];
__device__ __align__(16) __half g_ao_h[MROWS * DIMM];
__device__ __align__(16) __half g_wq_h[3 * DIMM * DIMM];  // qkv_w^T  [1152][384]
__device__ __align__(16) __half g_wp_h[DIMM * DIMM];      // proj_w^T [384][384]

union F4U { float4 f; u64 u[2]; };

__device__ __forceinline__ u64 pack2(float a, float b) {
    u64 r; asm("mov.b64 %0,{%1,%2};" : "=l"(r) : "f"(a), "f"(b)); return r;
}
__device__ __forceinline__ float2 unpk2(u64 v) {
    float2 r; asm("mov.b64 {%0,%1},%2;" : "=f"(r.x), "=f"(r.y) : "l"(v)); return r;
}
__device__ __forceinline__ void fma2(u64& d, u64 a, u64 b) {
    asm("fma.rn.f32x2 %0,%1,%2,%0;" : "+l"(d) : "l"(a), "l"(b));
}
__device__ __forceinline__ void mul2(u64& d, u64 s) {
    asm("mul.rn.f32x2 %0,%0,%1;" : "+l"(d) : "l"(s));
}

// ---------------------------------------------------------------------------
// K1: mask bit-pack with inline dtype detection (smem broadcast per block).
// ---------------------------------------------------------------------------
__global__ __launch_bounds__(256)
void convert_mask_kernel(const void* __restrict__ mraw)
{
    __shared__ int smode;
    if (threadIdx.x == 0) {
        const unsigned* mm = (const unsigned*)mraw;
        bool sawF32 = false, sawHigh = false;
        for (int i = 0; i < 256; i++) {
            unsigned w = mm[i];
            if (w == 0x3F800000u) sawF32 = true;
            else if (w != 0u && w != 1u) sawHigh = true;
        }
        smode = sawHigh ? 0 : (sawF32 ? 2 : 1);
    }
    __syncthreads();
    const int mode = smode;

    int idx = blockIdx.x * blockDim.x + threadIdx.x;
    if (idx >= NWIN * LWIN * MWPR) return;
    int wi  = idx % MWPR;
    int row = idx / MWPR;
    size_t base = (size_t)(row / LWIN) * LWIN * LWIN + (size_t)(row % LWIN) * LWIN;
    unsigned bits = 0;
    for (int b = 0; b < 32; b++) {
        int j = wi * 32 + b;
        bool mb;
        if (j >= LWIN)          mb = true;
        else if (mode == 0)     mb = ((const unsigned char*)mraw)[base + j] != 0;
        else if (mode == 1)     mb = ((const int*)mraw)[base + j] != 0;
        else                    mb = ((const float*)mraw)[base + j] != 0.0f;
        bits |= (mb ? 1u : 0u) << b;
    }
    g_maskbits[idx] = bits;
}

__global__ __launch_bounds__(BI)
void bias_kernel(const int* __restrict__ rel_idx, const float* __restrict__ table)
{
    int h = blockIdx.x / BJ, j = blockIdx.x % BJ;
    int i = threadIdx.x;
    float v = 0.0f;
    if (j < LWIN && i < LWIN)
        v = __ldg(table + (size_t)__ldg(rel_idx + (size_t)i * LWIN + j) * NHEAD + h);
    g_bias[((size_t)h * BJ + j) * BI + i] = v;
}

// ---------------------------------------------------------------------------
// fp16 convert of x -> g_x_h (vectorized by 4)
// ---------------------------------------------------------------------------
__global__ __launch_bounds__(256)
void split_kernel(const float* __restrict__ in)
{
    const int n4 = MROWS * DIMM / 4;
    int i = blockIdx.x * 256 + threadIdx.x;
    if (i >= n4) return;
    float4 v = ((const float4*)in)[i];
    ((__half2*)g_x_h)[i * 2]     = __floats2half2_rn(v.x, v.y);
    ((__half2*)g_x_h)[i * 2 + 1] = __floats2half2_rn(v.z, v.w);
}

// combined transpose+convert of both weights: blockIdx.x < 36 -> qkv, else proj.
__global__ __launch_bounds__(256)
void tsplit_kernel(const float* __restrict__ wq, const float* __restrict__ wp)
{
    __shared__ float tile[32][33];
    const int mode = (blockIdx.x >= 36) ? 1 : 0;
    const int bx   = mode ? (blockIdx.x - 36) : blockIdx.x;
    const float* in = mode ? wp : wq;
    const int N = mode ? DIMM : 3 * DIMM;
    __half* dst = mode ? g_wp_h : g_wq_h;
    int n0 = bx * 32, k0 = blockIdx.y * 32;
    int tx = threadIdx.x, ty = threadIdx.y;
#pragma unroll
    for (int i = 0; i < 32; i += 8)
        tile[ty + i][tx] = in[(size_t)(k0 + ty + i) * N + n0 + tx];
    __syncthreads();
#pragma unroll
    for (int i = 0; i < 32; i += 8)
        dst[(size_t)(n0 + ty + i) * DIMM + k0 + tx] = __float2half(tile[tx][ty + i]);
}

// ---------------------------------------------------------------------------
// fp16 single-pass WMMA GEMM, double-buffered k-step 32, fused epilogues.
// mode 0: x @ wq^T (N=1152) -> scatter g_q/g_k/g_v (Q pre-scaled)
// mode 1: ao @ wp^T (N=384) -> + proj_b -> out
// Block 64x128, 256 thr (8 warps, warp tile 32x32).
// smem: 2 stages x (64+128) rows x LDB half = 30,720 B; epilogue 36,864 B.
// ---------------------------------------------------------------------------
#define STAGE_HALF (192 * LDB)                  // 7680 half = 15360 B per stage
#define GEMM_SMEM  (8 * 32 * CPAD * 4)          // 36864 B (max of both phases)

__global__ __launch_bounds__(256)
void wmma_gemm_kernel(int mode, const float* __restrict__ pb,
                      float* __restrict__ out)
{
    extern __shared__ __align__(16) __half sm[];
    float* Cs = (float*)sm;                     // epilogue reuse

    const __half* Ah = mode ? g_ao_h : g_x_h;
    const __half* Bh = mode ? g_wp_h : g_wq_h;

    const int m0 = blockIdx.y * 64, n0 = blockIdx.x * 128;
    const int tid = threadIdx.x;
    const int lane = tid & 31, w = tid >> 5;
    const int wm = w >> 2, wn = w & 3;

    wmma::fragment<wmma::accumulator, 16, 16, 16, float> c[2][2];
#pragma unroll
    for (int i = 0; i < 2; i++)
#pragma unroll
        for (int j = 0; j < 2; j++) wmma::fill_fragment(c[i][j], 0.0f);

    // stage layout (half offsets within stage): A 0 (64*LDB), B 2560 (128*LDB)
    auto load_stage = [&](int s, int kc) {
        __half* A = sm + s * STAGE_HALF;
        __half* B = A + 64 * LDB;
        {
            int row = tid >> 2, c8 = (tid & 3) << 3;
            *(uint4*)&A[row * LDB + c8] =
                *(const uint4*)&Ah[(size_t)(m0 + row) * DIMM + kc + c8];
        }
#pragma unroll
        for (int u = 0; u < 2; u++) {
            int e = tid + u * 256;
            int row = e >> 2, c8 = (e & 3) << 3;
            *(uint4*)&B[row * LDB + c8] =
                *(const uint4*)&Bh[(size_t)(n0 + row) * DIMM + kc + c8];
        }
    };

    load_stage(0, 0);
    __syncthreads();

    for (int it = 0; it < DIMM / KSTEP; it++) {         // 12 iterations
        const int cur = it & 1;
        if (it < DIMM / KSTEP - 1) load_stage(cur ^ 1, (it + 1) * KSTEP);

        const __half* A = sm + cur * STAGE_HALF;
        const __half* B = A + 64 * LDB;

#pragma unroll
        for (int ks = 0; ks < 2; ks++) {
            const int ko = ks * 16;
            wmma::fragment<wmma::matrix_a, 16, 16, 16, __half, wmma::row_major> a[2];
            wmma::fragment<wmma::matrix_b, 16, 16, 16, __half, wmma::col_major> b[2];
#pragma unroll
            for (int i = 0; i < 2; i++)
                wmma::load_matrix_sync(a[i], &A[(wm * 32 + i * 16) * LDB + ko], LDB);
#pragma unroll
            for (int j = 0; j < 2; j++)
                wmma::load_matrix_sync(b[j], &B[(wn * 32 + j * 16) * LDB + ko], LDB);
#pragma unroll
            for (int i = 0; i < 2; i++)
#pragma unroll
                for (int j = 0; j < 2; j++)
                    wmma::mma_sync(c[i][j], a[i], b[j], c[i][j]);
        }
        __syncthreads();
    }

    // epilogue: fragments -> Cs (per-warp 32xCPAD tile) -> fused writeout
    float* ct = Cs + w * (32 * CPAD);
#pragma unroll
    for (int i = 0; i < 2; i++)
#pragma unroll
        for (int j = 0; j < 2; j++)
            wmma::store_matrix_sync(ct + i * 16 * CPAD + j * 16, c[i][j], CPAD,
                                    wmma::mem_row_major);
    __syncwarp();

    const int colbase = n0 + wn * 32;     // multiple of 32 -> head aligned
    if (mode == 0) {
        const int three = colbase / DIMM;
        const int cm = colbase - three * DIMM;
        const int h = cm >> 5;
        float* dst = (three == 0) ? g_q : (three == 1 ? g_k : g_v);
        const float sc = (three == 0) ? QK_SCALE : 1.0f;
#pragma unroll 4
        for (int r = 0; r < 32; r++) {
            int mg = m0 + wm * 32 + r;
            int n = mg / LWIN, l = mg - n * LWIN;
            dst[(size_t)((n * NHEAD + h) * LWIN + l) * HEADD + lane] =
                ct[r * CPAD + lane] * sc;
        }
    } else {
        const float bv = pb[colbase + lane];
#pragma unroll 4
        for (int r = 0; r < 32; r++) {
            int mg = m0 + wm * 32 + r;
            out[(size_t)mg * DIMM + colbase + lane] = ct[r * CPAD + lane] + bv;
        }
    }
}

// ---------------------------------------------------------------------------
// K2: flash attention — proven config; epilogue writes fp16 g_ao_h.
// ---------------------------------------------------------------------------
#define ATTN_SMEM_BYTES (BJ * HEADD * 2 * 4)   // 90112

__global__ __launch_bounds__(BJ, 1)
void attn_kernel()
{
    extern __shared__ float smem[];
    float* Ks = smem;
    float* Vs = smem + BJ * HEADD;

    const int h   = blockIdx.x;
    const int win = blockIdx.y;
    const int tid = threadIdx.x;
    const int rowc = (tid < LWIN) ? tid : (LWIN - 1);
    const size_t base = (size_t)(win * NHEAD + h) * LWIN * HEADD;

    for (int idx = tid; idx < LWIN * HEADD; idx += BJ) {
        Ks[idx] = g_k[base + idx];
        Vs[idx] = g_v[base + idx];
    }
    for (int idx = LWIN * HEADD + tid; idx < BJ * HEADD; idx += BJ) {
        Ks[idx] = 0.0f;
        Vs[idx] = 0.0f;
    }
    __syncthreads();

    F4U q[8];
    const float4* qp = (const float4*)(g_q + base + (size_t)rowc * HEADD);
#pragma unroll
    for (int i = 0; i < 8; i++) q[i].f = qp[i];

    u64 O[16];
#pragma unroll
    for (int i = 0; i < 16; i++) O[i] = 0ULL;
    float m = -1e30f, l = 0.0f;

    const unsigned* mrow = g_maskbits + (size_t)(win * LWIN + rowc) * MWPR;
    const float*    brow = g_bias + (size_t)h * BJ * BI + rowc;

    for (int jc = 0; jc < NCHUNK; jc++) {
        const unsigned mw = __ldg(mrow + jc);
        const float*   bp = brow + (size_t)(jc * 32) * BI;

        float s[32];
#pragma unroll
        for (int jj = 0; jj < 32; jj++) {
            const F4U* kp = (const F4U*)(Ks + (jc * 32 + jj) * HEADD);
            u64 a0 = 0ULL, a1 = 0ULL;
#pragma unroll
            for (int c4 = 0; c4 < 8; c4 += 2) {
                F4U k0 = kp[c4], k1 = kp[c4 + 1];
                fma2(a0, q[c4].u[0],     k0.u[0]);
                fma2(a0, q[c4].u[1],     k0.u[1]);
                fma2(a1, q[c4 + 1].u[0], k1.u[0]);
                fma2(a1, q[c4 + 1].u[1], k1.u[1]);
            }
            float2 e0 = unpk2(a0), e1 = unpk2(a1);
            float sv = (e0.x + e1.x) + (e0.y + e1.y) + __ldg(bp + (size_t)jj * BI);
            if ((mw >> jj) & 1u) sv = -1e30f;
            s[jj] = sv;
        }

        float mc = s[0];
#pragma unroll
        for (int jj = 1; jj < 32; jj++) mc = fmaxf(mc, s[jj]);
        float mn = fmaxf(m, mc);
        float scale = __expf(m - mn);
        m = mn;
        l *= scale;
        u64 sc2 = pack2(scale, scale);
#pragma unroll
        for (int i = 0; i < 16; i++) mul2(O[i], sc2);

#pragma unroll
        for (int jj = 0; jj < 32; jj++) {
            float p = __expf(s[jj] - m);
            l += p;
            u64 p2 = pack2(p, p);
            const F4U* vp = (const F4U*)(Vs + (jc * 32 + jj) * HEADD);
#pragma unroll
            for (int c4 = 0; c4 < 8; c4++) {
                F4U v4 = vp[c4];
                fma2(O[c4 * 2],     p2, v4.u[0]);
                fma2(O[c4 * 2 + 1], p2, v4.u[1]);
            }
        }
    }

    // fused epilogue: normalize + fp16 convert -> g_ao_h
    const float inv = 1.0f / l;
    const size_t rb = ((size_t)(win * LWIN) + rowc) * DIMM + h * HEADD;
#pragma unroll
    for (int i = 0; i < 8; i++) {
        float2 eA = unpk2(O[i * 2]), eB = unpk2(O[i * 2 + 1]);
        __half2* ph = (__half2*)(g_ao_h + rb + i * 4);
        ph[0] = __floats2half2_rn(eA.x * inv, eA.y * inv);
        ph[1] = __floats2half2_rn(eB.x * inv, eB.y * inv);
    }
}

extern "C" void kernel_launch(void* const* d_in, const int* in_sizes, int n_in,
                              void* d_out, int out_size)
{
    const float* x       = (const float*)d_in[0];
    const float* qkv_w   = (const float*)d_in[1];
    const float* table   = (const float*)d_in[2];
    const float* proj_w  = (const float*)d_in[3];
    const float* proj_b  = (const float*)d_in[4];
    const void*  mask    = d_in[5];
    const int*   rel_idx = (const int*)d_in[6];
    float*       out     = (float*)d_out;

    // launch order chosen so ncu (-s 5 -c 1) profiles attn_kernel (#6)
    convert_mask_kernel<<<(NWIN * LWIN * MWPR + 255) / 256, 256>>>(mask);    // 1
    bias_kernel<<<NHEAD * BJ, BI>>>(rel_idx, table);                         // 2
    const int n4 = MROWS * DIMM / 4;
    split_kernel<<<(n4 + 255) / 256, 256>>>(x);                              // 3
    tsplit_kernel<<<dim3(48, 12), dim3(32, 8)>>>(qkv_w, proj_w);             // 4

    cudaFuncSetAttribute(wmma_gemm_kernel, cudaFuncAttributeMaxDynamicSharedMemorySize,
                         GEMM_SMEM);
    wmma_gemm_kernel<<<dim3(9, 343), 256, GEMM_SMEM>>>(0, nullptr, nullptr); // 5 (qkv)

    cudaFuncSetAttribute(attn_kernel, cudaFuncAttributeMaxDynamicSharedMemorySize,
                         ATTN_SMEM_BYTES);
    attn_kernel<<<dim3(NHEAD, NWIN), BJ, ATTN_SMEM_BYTES>>>();               // 6 (profiled)

    wmma_gemm_kernel<<<dim3(3, 343), 256, GEMM_SMEM>>>(1, proj_b, out);      // 7 (proj)
}